// round 15
// baseline (speedup 1.0000x reference)
#include <cuda_runtime.h>
#include <cuda_bf16.h>
#include <cstdint>

// ---------------------------------------------------------------------------
// Scratch (static __device__ arrays; no allocation anywhere)
// ---------------------------------------------------------------------------
__device__ float g_xz[176947200];            // time-major xz, max layer1: 96*3600*512
__device__ float g_z[29491200];              // recurrent pre-activation, max 16*3600*512
__device__ float g_h[7372800];               // fp32 h state (dense head input)
__device__ float g_c[7372800];               // c state
__device__ __nv_bfloat16 g_hhi[7372800];     // bf16 hi/lo h state (layer-3 conv input)
__device__ __nv_bfloat16 g_hlo[7372800];
__device__ __nv_bfloat16 g_hs1hi[44236800];  // layer1 output seq 96*3600*128
__device__ __nv_bfloat16 g_hs1lo[44236800];
__device__ __nv_bfloat16 g_hs2hi[19267584];  // layer2 output seq 96*3136*64
__device__ __nv_bfloat16 g_hs2lo[19267584];
__device__ __nv_bfloat16 g_wp[3276800];      // prepped weights [chunk][Co][64 bf16]
__device__ float g_dp[1048576];
__device__ float g_d1[16384];
__device__ float g_d2[16384];

// ---------------------------------------------------------------------------
// PTX helpers (portable subset only — no tcgen05 on this build's PTX target)
// ---------------------------------------------------------------------------
__device__ __forceinline__ void cp16cg(uint32_t dst, const void* src)
{
    asm volatile("cp.async.cg.shared.global [%0], [%1], 16;"
                 :: "r"(dst), "l"(src));
}
__device__ __forceinline__ void cp16z(uint32_t dst, const void* src, int sz)
{
    asm volatile("cp.async.cg.shared.global [%0], [%1], 16, %2;"
                 :: "r"(dst), "l"(src), "r"(sz));
}
__device__ __forceinline__ void cp_commit()
{
    asm volatile("cp.async.commit_group;" ::: "memory");
}
__device__ __forceinline__ void cp_wait2()
{
    asm volatile("cp.async.wait_group 2;" ::: "memory");
}

__device__ __forceinline__ void ldsm4(uint32_t& r0, uint32_t& r1, uint32_t& r2,
                                      uint32_t& r3, uint32_t addr)
{
    asm volatile("ldmatrix.sync.aligned.m8n8.x4.shared.b16 {%0,%1,%2,%3}, [%4];"
                 : "=r"(r0), "=r"(r1), "=r"(r2), "=r"(r3) : "r"(addr));
}

__device__ __forceinline__ void mma_bf16(float* d, const uint32_t* a,
                                         uint32_t b0, uint32_t b1)
{
    asm volatile("mma.sync.aligned.m16n8k16.row.col.f32.bf16.bf16.f32 "
                 "{%0,%1,%2,%3}, {%4,%5,%6,%7}, {%8,%9}, {%0,%1,%2,%3};"
                 : "+f"(d[0]), "+f"(d[1]), "+f"(d[2]), "+f"(d[3])
                 : "r"(a[0]), "r"(a[1]), "r"(a[2]), "r"(a[3]), "r"(b0), "r"(b1));
}

// ---------------------------------------------------------------------------
// Layer-1 input conv (Cin=5, 5x5 VALID, 64x64 -> 60x60, Co=512), FFMA.
// Reduction flattened: k = kp*5 + c (= W's native row order), K=128 (125+3
// zero slots), 8 tiles of 16.  Output time-major remapped, + bias.
// ---------------------------------------------------------------------------
__global__ __launch_bounds__(256, 2)
void conv_gemm_l1(const float* __restrict__ X, const float* __restrict__ W,
                  const float* __restrict__ bias, float* __restrict__ Out)
{
    __shared__ __align__(16) float As[16][128];
    __shared__ __align__(16) float Bs[16][128];
    __shared__ int sY[128], sX[128], sBase[128];

    const int t  = threadIdx.x;
    const int m0 = blockIdx.x * 128;
    const int n0 = blockIdx.y * 128;
    const int P  = 3600;

    if (t < 128) {
        int pix = m0 + t;
        int n = pix / P;
        int r = pix - n * P;
        int y = r / 60;
        sY[t] = y;
        sX[t] = r - y * 60;
        sBase[t] = n * 64 * 64 * 5;
    }
    __syncthreads();

    float acc[8][8];
    #pragma unroll
    for (int i = 0; i < 8; ++i)
        #pragma unroll
        for (int j = 0; j < 8; ++j) acc[i][j] = 0.f;

    const int tr = t & 15, tc = t >> 4;
    const int rowA = t >> 1;
    const int kk0  = (t & 1) * 8;
    const int aBase = sBase[rowA];
    const int aY = sY[rowA], aX = sX[rowA];

    for (int kt = 0; kt < 8; ++kt) {
        __syncthreads();
        #pragma unroll
        for (int j = 0; j < 8; ++j) {
            int kk = kk0 + j;
            int k  = kt * 16 + kk;
            float v = 0.f;
            if (k < 125) {
                int kp = k / 5;
                int c  = k - kp * 5;
                int ky = kp / 5;
                int kx = kp - ky * 5;
                v = X[aBase + ((aY + ky) * 64 + (aX + kx)) * 5 + c];
            }
            As[kk][rowA ^ ((kk >> 2) << 3)] = v;
        }
        #pragma unroll
        for (int it = 0; it < 2; ++it) {
            int idx = t + it * 256;
            int kk  = idx >> 5;
            int col = (idx & 31) << 2;
            int k   = kt * 16 + kk;
            float4 v = make_float4(0.f, 0.f, 0.f, 0.f);
            if (k < 125)
                v = *(const float4*)(W + (size_t)k * 512 + n0 + col);
            *(float4*)&Bs[kk][col] = v;
        }
        __syncthreads();
        #pragma unroll
        for (int kk = 0; kk < 16; ++kk) {
            const int sw = (kk & 12) << 1;
            float4 a0 = *(const float4*)&As[kk][(tr * 8) ^ sw];
            float4 a1 = *(const float4*)&As[kk][((tr * 8) ^ sw) + 4];
            float4 b0 = *(const float4*)&Bs[kk][tc * 8];
            float4 b1 = *(const float4*)&Bs[kk][tc * 8 + 4];
            float a[8] = {a0.x, a0.y, a0.z, a0.w, a1.x, a1.y, a1.z, a1.w};
            float b[8] = {b0.x, b0.y, b0.z, b0.w, b1.x, b1.y, b1.z, b1.w};
            #pragma unroll
            for (int i = 0; i < 8; ++i)
                #pragma unroll
                for (int j = 0; j < 8; ++j)
                    acc[i][j] = fmaf(a[i], b[j], acc[i][j]);
        }
    }

    float bv[8];
    #pragma unroll
    for (int j = 0; j < 8; ++j) bv[j] = bias[n0 + tc * 8 + j];
    #pragma unroll
    for (int i = 0; i < 8; ++i) {
        int pix = m0 + tr * 8 + i;
        int n = pix / P;
        int p = pix - n * P;
        int b = n / 6;
        int tt = n - b * 6;
        size_t ob = ((size_t)(tt * 16 + b) * P + p) * 512 + n0 + tc * 8;
        #pragma unroll
        for (int j4 = 0; j4 < 8; j4 += 4) {
            float4 o;
            o.x = acc[i][j4 + 0] + bv[j4 + 0];
            o.y = acc[i][j4 + 1] + bv[j4 + 1];
            o.z = acc[i][j4 + 2] + bv[j4 + 2];
            o.w = acc[i][j4 + 3] + bv[j4 + 3];
            *(float4*)(Out + ob + j4) = o;
        }
    }
}

// ---------------------------------------------------------------------------
// Weight prep: fp32 W [kp][c][Co] -> [chunk][Co rows][128B] swizzled images.
// Row n of chunk c: 16B slots [hi k0..31 | lo k0..31], slot index ^ (n&7).
// ---------------------------------------------------------------------------
__global__ void wprep_kernel(const float* __restrict__ W, __nv_bfloat16* __restrict__ Wp,
                             int Cin, int Co, int nchunk)
{
    int c = blockIdx.x;
    int cpk = Cin >> 5;
    int kp = c / cpk, c0 = (c - kp * cpk) << 5;
    for (int n = threadIdx.x; n < Co; n += blockDim.x) {
        __nv_bfloat16* dst = Wp + ((size_t)c * Co + n) * 64;
        int sw = n & 7;
        for (int k = 0; k < 32; ++k) {
            float w = W[(size_t)(kp * Cin + c0 + k) * Co + n];
            __nv_bfloat16 hi = __float2bfloat16(w);
            __nv_bfloat16 lo = __float2bfloat16(w - __bfloat162float(hi));
            int ch = k >> 3, off = k & 7;
            dst[(( ch      ^ sw) << 3) + off] = hi;
            dst[(((ch + 4) ^ sw) << 3) + off] = lo;
        }
    }
}

// ---------------------------------------------------------------------------
// Tensor-core implicit-GEMM conv, bf16x3 fp32 emulation.
// ONE 512-thread CTA per SM, tile 128(M) x 256(N); 16 warps in 4m x 4n,
// warp tile 32x64.  NEW: 4-stage cp.async ring (192 KB smem), wait_group 2 —
// a full prefetched window is always resident behind the compute window.
// 2 chunks per barrier pair; tail uses unconditional empty commits so the
// group ledger stays uniform (pending == 4 groups at every wait).
// A-source: xbase = nbi*xsb + xoff (reads h straight from sequence buffers).
// Requires M%128==0, Co%256==0, Cin%32==0, nchunk even and >= 4.
// ---------------------------------------------------------------------------
#define CM_STAGE 49152
#define CM_SMEM  (4 * CM_STAGE)

__global__ __launch_bounds__(512, 1)
void conv_mma(const __nv_bfloat16* __restrict__ Xhi, const __nv_bfloat16* __restrict__ Xlo,
              const __nv_bfloat16* __restrict__ Wp,
              const float* __restrict__ bias, const float* __restrict__ addend,
              float* __restrict__ Out,
              int Hi, int Wi, int Cin, int Co, int Ho, int Wo,
              int pad, int T, int Bo, int nchunk, int cpkShift,
              int xsb, int xoff)
{
    extern __shared__ __align__(16) char smem[];
    const uint32_t sbase = (uint32_t)__cvta_generic_to_shared(smem);
    const int t = threadIdx.x;
    const int m0 = blockIdx.x * 128, n0 = blockIdx.y * 256;
    const int P = Ho * Wo;
    const int cpkMask = (1 << cpkShift) - 1;

    // A-loader identity: row r = t>>2, half = (t>>1)&1, quarter q0 = (t&1)*2
    const int r    = t >> 2;
    const int half = (t >> 1) & 1;
    const int q0   = (t & 1) * 2;
    const int pix  = m0 + r;
    const int nbi  = pix / P;
    const int rr   = pix - nbi * P;
    const int py   = rr / Wo;
    const int px   = rr - py * Wo;
    const __nv_bfloat16* Xsrc = half ? Xlo : Xhi;
    const size_t xbase = (size_t)nbi * xsb + xoff;
    const uint32_t arow = (uint32_t)r * 128;
    const int rsw = r & 7;

    const int lane = t & 31, wid = t >> 5;
    const int warp_m = wid & 3, warp_n = wid >> 2;
    const int khStag = (wid & 1) << 1;

    float acc[2][8][4];
    #pragma unroll
    for (int i = 0; i < 2; ++i)
        #pragma unroll
        for (int j = 0; j < 8; ++j)
            #pragma unroll
            for (int k = 0; k < 4; ++k) acc[i][j][k] = 0.f;

    const int rA  = warp_m * 32 + (lane & 15);
    const int swA = rA & 7;
    const int rB  = warp_n * 64 + (lane & 7) + ((lane >> 4) << 3);
    const int swB = rB & 7;
    const int aSel = lane >> 4;
    const int bSel = (lane >> 3) & 1;

    auto issue_chunk = [&](int c, int s) {
        const uint32_t stg = sbase + (uint32_t)s * CM_STAGE;
        int kp = c >> cpkShift;
        int c0 = (c & cpkMask) << 5;
        int ky = kp / 5, kx = kp - ky * 5;
        int iy = py + ky - pad, ix = px + kx - pad;
        bool ok = ((unsigned)iy < (unsigned)Hi) && ((unsigned)ix < (unsigned)Wi);
        const char* src = (const char*)(Xsrc + (ok ? (xbase + (size_t)(iy * Wi + ix) * Cin + c0)
                                                   : (size_t)0));
        int sz = ok ? 16 : 0;
        #pragma unroll
        for (int i = 0; i < 2; ++i) {
            int q = q0 + i;
            int ch = ((half << 2) + q) ^ rsw;
            cp16z(stg + arow + ch * 16, src + q * 16, sz);
        }
        const char* bsrc = (const char*)Wp + ((size_t)c * Co + n0) * 128;
        const uint32_t bb = stg + 16384;
        #pragma unroll
        for (int i = 0; i < 4; ++i)
            cp16cg(bb + (t * 4 + i) * 16, bsrc + (t * 4 + i) * 16);
    };

    auto compute = [&](int s) {
        uint32_t As = sbase + (uint32_t)s * CM_STAGE;
        uint32_t Bs = As + 16384;
        #pragma unroll
        for (int it = 0; it < 2; ++it) {
            const int kh = khStag ^ (it << 1);
            uint32_t aH[2][4], aL[2][4], bH[4][4], bL[4][4];
            {
                uint32_t aaddr = As + rA * 128 + ((((kh) + aSel) ^ swA) << 4);
                ldsm4(aH[0][0], aH[0][1], aH[0][2], aH[0][3], aaddr);
                ldsm4(aH[1][0], aH[1][1], aH[1][2], aH[1][3], aaddr + 2048);
            }
            #pragma unroll
            for (int nt = 0; nt < 4; ++nt) {
                uint32_t baddr = Bs + (rB + nt * 16) * 128 + ((((kh) + bSel) ^ swB) << 4);
                ldsm4(bH[nt][0], bH[nt][1], bH[nt][2], bH[nt][3], baddr);
            }
            #pragma unroll
            for (int j = 0; j < 8; ++j) {
                uint32_t b0 = bH[j >> 1][(j & 1) * 2];
                uint32_t b1 = bH[j >> 1][(j & 1) * 2 + 1];
                mma_bf16(acc[0][j], aH[0], b0, b1);
                mma_bf16(acc[1][j], aH[1], b0, b1);
            }
            {
                uint32_t aaddr = As + rA * 128 + ((((kh + 4) + aSel) ^ swA) << 4);
                ldsm4(aL[0][0], aL[0][1], aL[0][2], aL[0][3], aaddr);
                ldsm4(aL[1][0], aL[1][1], aL[1][2], aL[1][3], aaddr + 2048);
            }
            #pragma unroll
            for (int nt = 0; nt < 4; ++nt) {
                uint32_t baddr = Bs + (rB + nt * 16) * 128 + ((((kh + 4) + bSel) ^ swB) << 4);
                ldsm4(bL[nt][0], bL[nt][1], bL[nt][2], bL[nt][3], baddr);
            }
            #pragma unroll
            for (int j = 0; j < 8; ++j) {
                uint32_t b0 = bH[j >> 1][(j & 1) * 2];
                uint32_t b1 = bH[j >> 1][(j & 1) * 2 + 1];
                mma_bf16(acc[0][j], aL[0], b0, b1);
                mma_bf16(acc[1][j], aL[1], b0, b1);
            }
            #pragma unroll
            for (int j = 0; j < 8; ++j) {
                uint32_t b0 = bL[j >> 1][(j & 1) * 2];
                uint32_t b1 = bL[j >> 1][(j & 1) * 2 + 1];
                mma_bf16(acc[0][j], aH[0], b0, b1);
                mma_bf16(acc[1][j], aH[1], b0, b1);
            }
        }
    };

    // ---- prologue: fill all 4 stages (one group per chunk) ----
    issue_chunk(0, 0); cp_commit();
    issue_chunk(1, 1); cp_commit();
    issue_chunk(2, 2); cp_commit();
    issue_chunk(3, 3); cp_commit();

    // ---- mainloop: 2 chunks per barrier pair, 2-window prefetch depth.
    //      stage(c) = c & 3.  Unconditional commits keep pending == 4. ----
    int s = 0;
    for (int c = 0; c < nchunk; c += 2) {
        cp_wait2();               // chunks c, c+1 complete; c+2, c+3 in flight
        __syncthreads();
        int s1 = (s + 1) & 3;
        compute(s);
        compute(s1);
        __syncthreads();
        if (c + 4 < nchunk) issue_chunk(c + 4, s);
        cp_commit();
        if (c + 5 < nchunk) issue_chunk(c + 5, s1);
        cp_commit();
        s = (s1 + 1) & 3;
    }

    // ---- epilogue ----
    const int colB = n0 + warp_n * 64 + (lane & 3) * 2;
    #pragma unroll
    for (int mt = 0; mt < 2; ++mt) {
        int r0g = m0 + warp_m * 32 + mt * 16 + (lane >> 2);
        #pragma unroll
        for (int hrow = 0; hrow < 2; ++hrow) {
            int pix2 = r0g + hrow * 8;
            size_t opix;
            if (T > 1) {
                int nb2 = pix2 / P, p = pix2 - nb2 * P;
                int b = nb2 / T, tt = nb2 - b * T;
                opix = (size_t)(tt * Bo + b) * P + p;
            } else {
                opix = (size_t)pix2;
            }
            size_t rowoff = opix * Co;
            #pragma unroll
            for (int j = 0; j < 8; ++j) {
                int col = colB + j * 8;
                float v0 = acc[mt][j][hrow * 2 + 0];
                float v1 = acc[mt][j][hrow * 2 + 1];
                if (addend) {
                    float2 ad = *(const float2*)(addend + rowoff + col);
                    v0 += ad.x; v1 += ad.y;
                } else {
                    v0 += bias[col]; v1 += bias[col + 1];
                }
                *(float2*)(Out + rowoff + col) = make_float2(v0, v1);
            }
        }
    }
}

// ---------------------------------------------------------------------------
// LSTM gate pointwise (keras gate order i,f,c,o).  zeroC==1 -> c_prev = 0.
// h / hhi,hlo / hshi,hslo each written only when their pointer is non-null.
// ---------------------------------------------------------------------------
__device__ __forceinline__ float hsig(float x)
{
    return fminf(1.f, fmaxf(0.f, fmaf(x, 0.2f, 0.5f)));
}

__global__ __launch_bounds__(256)
void gates_kernel(const float* __restrict__ z, float* __restrict__ c,
                  float* __restrict__ h,
                  __nv_bfloat16* __restrict__ hhi, __nv_bfloat16* __restrict__ hlo,
                  __nv_bfloat16* __restrict__ hshi, __nv_bfloat16* __restrict__ hslo,
                  int total4, int F, int P, int T, int ts, int zeroC)
{
    int idx = blockIdx.x * blockDim.x + threadIdx.x;
    if (idx >= total4) return;
    int e   = idx << 2;
    int pix = e / F;
    int f   = e - pix * F;
    size_t zb = (size_t)pix * (F << 2) + f;
    float4 zi = *(const float4*)(z + zb);
    float4 zf = *(const float4*)(z + zb + F);
    float4 zc = *(const float4*)(z + zb + 2 * F);
    float4 zo = *(const float4*)(z + zb + 3 * F);
    float4 cn, hn;
    if (zeroC) {
        cn.x = hsig(zi.x) * tanhf(zc.x);
        cn.y = hsig(zi.y) * tanhf(zc.y);
        cn.z = hsig(zi.z) * tanhf(zc.z);
        cn.w = hsig(zi.w) * tanhf(zc.w);
    } else {
        float4 cp = *(const float4*)(c + e);
        cn.x = hsig(zf.x) * cp.x + hsig(zi.x) * tanhf(zc.x);
        cn.y = hsig(zf.y) * cp.y + hsig(zi.y) * tanhf(zc.y);
        cn.z = hsig(zf.z) * cp.z + hsig(zi.z) * tanhf(zc.z);
        cn.w = hsig(zf.w) * cp.w + hsig(zi.w) * tanhf(zc.w);
    }
    hn.x = hsig(zo.x) * tanhf(cn.x);
    hn.y = hsig(zo.y) * tanhf(cn.y);
    hn.z = hsig(zo.z) * tanhf(cn.z);
    hn.w = hsig(zo.w) * tanhf(cn.w);
    *(float4*)(c + e) = cn;
    if (h) *(float4*)(h + e) = hn;

    float hv[4] = {hn.x, hn.y, hn.z, hn.w};
    __nv_bfloat16 hi[4], lo[4];
    #pragma unroll
    for (int k = 0; k < 4; ++k) {
        hi[k] = __float2bfloat16(hv[k]);
        lo[k] = __float2bfloat16(hv[k] - __bfloat162float(hi[k]));
    }
    if (hhi) {
        #pragma unroll
        for (int k = 0; k < 4; ++k) { hhi[e + k] = hi[k]; hlo[e + k] = lo[k]; }
    }
    if (hshi) {
        int b = pix / P;
        int p = pix - b * P;
        size_t hsi = ((size_t)(b * T + ts) * P + p) * F + f;
        #pragma unroll
        for (int k = 0; k < 4; ++k) { hshi[hsi + k] = hi[k]; hslo[hsi + k] = lo[k]; }
    }
}

// ---------------------------------------------------------------------------
// Dense head (fp32, split-K, deterministic reduce)
// ---------------------------------------------------------------------------
__global__ __launch_bounds__(256)
void dense_splitk(const float* __restrict__ A, const float* __restrict__ Wt,
                  float* __restrict__ part, int K, int N, int kc)
{
    int col = blockIdx.x * 256 + threadIdx.x;
    int k0  = blockIdx.y * kc;
    int k1  = min(k0 + kc, K);
    float acc[16];
    #pragma unroll
    for (int b = 0; b < 16; ++b) acc[b] = 0.f;
    for (int k = k0; k < k1; ++k) {
        float w = Wt[(size_t)k * N + col];
        #pragma unroll
        for (int b = 0; b < 16; ++b)
            acc[b] = fmaf(A[(size_t)b * K + k], w, acc[b]);
    }
    size_t ob = (size_t)blockIdx.y * 16 * N;
    #pragma unroll
    for (int b = 0; b < 16; ++b)
        part[ob + (size_t)b * N + col] = acc[b];
}

__global__ __launch_bounds__(256)
void dense_reduce(const float* __restrict__ part, const float* __restrict__ bias,
                  float* __restrict__ out, int nsplit, int N, int do_relu)
{
    int i = blockIdx.x * blockDim.x + threadIdx.x;
    if (i >= 16 * N) return;
    float s = bias[i % N];
    for (int sp = 0; sp < nsplit; ++sp)
        s += part[(size_t)sp * 16 * N + i];
    out[i] = do_relu ? fmaxf(s, 0.f) : s;
}

__global__ void dense3_kernel(const float* __restrict__ A, const float* __restrict__ Wt,
                              const float* __restrict__ bias, float* __restrict__ out)
{
    int t = threadIdx.x;
    if (t >= 64) return;
    int b = t >> 2, n = t & 3;
    float acc = bias[n];
    #pragma unroll 8
    for (int k = 0; k < 1024; ++k)
        acc = fmaf(A[b * 1024 + k], Wt[k * 4 + n], acc);
    out[b * 4 + n] = acc;
}

// ---------------------------------------------------------------------------
// Host orchestration
// ---------------------------------------------------------------------------
static void recurrent_part(const float* Wh, __nv_bfloat16* wp,
                           float* xz, float* zb, float* hb, float* cb,
                           __nv_bfloat16* hhi, __nv_bfloat16* hlo,
                           __nv_bfloat16* hshi, __nv_bfloat16* hslo,
                           int B, int T, int Ho, int Wo, int F, int needH)
{
    const int Cin = F, Co = 4 * F, P = Ho * Wo;
    const int nchunk = 25 * (Cin >> 5);
    const int shift  = (Cin == 128) ? 2 : 1;
    wprep_kernel<<<nchunk, 256>>>(Wh, wp, Cin, Co, nchunk);
    const int nstate = B * P * F;
    const int tot4 = nstate / 4;
    for (int t = 0; t < T; ++t) {
        const float* zp;
        if (t == 0) {
            zp = xz;
        } else {
            const __nv_bfloat16 *ahi, *alo;
            int xsb, xoff;
            if (hshi) {             // layers 1-2: read h from sequence buffer
                ahi = hshi; alo = hslo;
                xsb = T * P * F; xoff = (t - 1) * P * F;
            } else {                // layer 3: dedicated state buffer
                ahi = hhi; alo = hlo;
                xsb = P * F; xoff = 0;
            }
            conv_mma<<<dim3(B * P / 128, Co / 256), 512, CM_SMEM>>>(
                ahi, alo, wp, nullptr, xz + (size_t)t * B * P * Co, zb,
                Ho, Wo, Cin, Co, Ho, Wo, 2, 1, B, nchunk, shift, xsb, xoff);
            zp = zb;
        }
        float* hout = (needH && t == T - 1) ? hb : nullptr;
        __nv_bfloat16* sthi = hshi ? nullptr : hhi;
        __nv_bfloat16* stlo = hshi ? nullptr : hlo;
        gates_kernel<<<(tot4 + 255) / 256, 256>>>(zp, cb, hout, sthi, stlo,
                                                  hshi, hslo, tot4, F, P, T, t, t == 0);
    }
}

extern "C" void kernel_launch(void* const* d_in, const int* in_sizes, int n_in,
                              void* d_out, int out_size)
{
    (void)in_sizes; (void)n_in; (void)out_size;
    const float* x   = (const float*)d_in[0];
    const float* Wx1 = (const float*)d_in[1];
    const float* Wh1 = (const float*)d_in[2];
    const float* b1  = (const float*)d_in[3];
    const float* Wx2 = (const float*)d_in[4];
    const float* Wh2 = (const float*)d_in[5];
    const float* b2  = (const float*)d_in[6];
    const float* Wx3 = (const float*)d_in[7];
    const float* Wh3 = (const float*)d_in[8];
    const float* b3  = (const float*)d_in[9];
    const float* Wd1 = (const float*)d_in[10];
    const float* bd1 = (const float*)d_in[11];
    const float* Wd2 = (const float*)d_in[12];
    const float* bd2 = (const float*)d_in[13];
    const float* Wd3 = (const float*)d_in[14];
    const float* bd3 = (const float*)d_in[15];
    float* out = (float*)d_out;

    float *xz, *zb, *hb, *cb, *dp, *dd1, *dd2;
    __nv_bfloat16 *hhi, *hlo, *hs1hi, *hs1lo, *hs2hi, *hs2lo, *wp;
    cudaGetSymbolAddress((void**)&xz,    g_xz);
    cudaGetSymbolAddress((void**)&zb,    g_z);
    cudaGetSymbolAddress((void**)&hb,    g_h);
    cudaGetSymbolAddress((void**)&cb,    g_c);
    cudaGetSymbolAddress((void**)&hhi,   g_hhi);
    cudaGetSymbolAddress((void**)&hlo,   g_hlo);
    cudaGetSymbolAddress((void**)&hs1hi, g_hs1hi);
    cudaGetSymbolAddress((void**)&hs1lo, g_hs1lo);
    cudaGetSymbolAddress((void**)&hs2hi, g_hs2hi);
    cudaGetSymbolAddress((void**)&hs2lo, g_hs2lo);
    cudaGetSymbolAddress((void**)&wp,    g_wp);
    cudaGetSymbolAddress((void**)&dp,    g_dp);
    cudaGetSymbolAddress((void**)&dd1,   g_d1);
    cudaGetSymbolAddress((void**)&dd2,   g_d2);

    cudaFuncSetAttribute(conv_mma, cudaFuncAttributeMaxDynamicSharedMemorySize, CM_SMEM);

    const int B = 16, T = 6;

    // ---- layer 1: (B,T,64,64,5) -> seq (B,T,60,60,128) ----
    conv_gemm_l1<<<dim3(B * T * 3600 / 128, 4), 256>>>(x, Wx1, b1, xz);
    recurrent_part(Wh1, wp, xz, zb, hb, cb, hhi, hlo, hs1hi, hs1lo,
                   B, T, 60, 60, 128, 0);

    // ---- layer 2: seq1 -> seq (B,T,56,56,64) ----
    wprep_kernel<<<100, 256>>>(Wx2, wp, 128, 256, 100);
    conv_mma<<<dim3(B * T * 3136 / 128, 1), 512, CM_SMEM>>>(
        hs1hi, hs1lo, wp, b2, nullptr, xz, 60, 60, 128, 256, 56, 56, 0, T, B, 100, 2,
        60 * 60 * 128, 0);
    recurrent_part(Wh2, wp, xz, zb, hb, cb, hhi, hlo, hs2hi, hs2lo,
                   B, T, 56, 56, 64, 0);

    // ---- layer 3: seq2 -> final h (B,52,52,64) ----
    wprep_kernel<<<50, 256>>>(Wx3, wp, 64, 256, 50);
    conv_mma<<<dim3(B * T * 2704 / 128, 1), 512, CM_SMEM>>>(
        hs2hi, hs2lo, wp, b3, nullptr, xz, 56, 56, 64, 256, 52, 52, 0, T, B, 50, 1,
        56 * 56 * 64, 0);
    recurrent_part(Wh3, wp, xz, zb, hb, cb, hhi, hlo, nullptr, nullptr,
                   B, T, 52, 52, 64, 1);

    // ---- dense head ----
    dense_splitk<<<dim3(4, 64), 256>>>(hb, Wd1, dp, 173056, 1024, 2704);
    dense_reduce<<<64, 256>>>(dp, bd1, dd1, 64, 1024, 1);
    dense_splitk<<<dim3(4, 8), 256>>>(dd1, Wd2, dp, 1024, 1024, 128);
    dense_reduce<<<64, 256>>>(dp, bd2, dd2, 8, 1024, 1);
    dense3_kernel<<<1, 64>>>(dd2, Wd3, bd3, out);
}

// round 16
// speedup vs baseline: 1.8068x; 1.8068x over previous
#include <cuda_runtime.h>
#include <cuda_fp16.h>
#include <cstdint>

// ---------------------------------------------------------------------------
// Scratch (static __device__ arrays; no allocation anywhere)
// ---------------------------------------------------------------------------
__device__ float g_xz[176947200];            // time-major xz, max layer1: 96*3600*512
__device__ float g_z[29491200];              // recurrent pre-activation, max 16*3600*512
__device__ float g_h[7372800];               // fp32 h state (dense head input)
__device__ float g_c[7372800];               // c state
__device__ __half g_hhi[7372800];            // fp16 hi/lo h state (layer-3 conv input)
__device__ __half g_hlo[7372800];
__device__ __half g_hs1hi[44236800];         // layer1 output seq 96*3600*128
__device__ __half g_hs1lo[44236800];
__device__ __half g_hs2hi[19267584];         // layer2 output seq 96*3136*64
__device__ __half g_hs2lo[19267584];
__device__ __half g_wp[3276800];             // prepped weights [chunk][Co][64 fp16]
__device__ float g_dp[1048576];
__device__ float g_d1[16384];
__device__ float g_d2[16384];

// ---------------------------------------------------------------------------
// PTX helpers (portable subset only — no tcgen05 on this build's PTX target)
// ---------------------------------------------------------------------------
__device__ __forceinline__ void cp16cg(uint32_t dst, const void* src)
{
    asm volatile("cp.async.cg.shared.global [%0], [%1], 16;"
                 :: "r"(dst), "l"(src));
}
__device__ __forceinline__ void cp16z(uint32_t dst, const void* src, int sz)
{
    asm volatile("cp.async.cg.shared.global [%0], [%1], 16, %2;"
                 :: "r"(dst), "l"(src), "r"(sz));
}
__device__ __forceinline__ void cp_commit()
{
    asm volatile("cp.async.commit_group;" ::: "memory");
}
__device__ __forceinline__ void cp_wait1()
{
    asm volatile("cp.async.wait_group 1;" ::: "memory");
}

__device__ __forceinline__ void ldsm4(uint32_t& r0, uint32_t& r1, uint32_t& r2,
                                      uint32_t& r3, uint32_t addr)
{
    asm volatile("ldmatrix.sync.aligned.m8n8.x4.shared.b16 {%0,%1,%2,%3}, [%4];"
                 : "=r"(r0), "=r"(r1), "=r"(r2), "=r"(r3) : "r"(addr));
}

__device__ __forceinline__ void mma_fp16(float* d, const uint32_t* a,
                                         uint32_t b0, uint32_t b1)
{
    asm volatile("mma.sync.aligned.m16n8k16.row.col.f32.f16.f16.f32 "
                 "{%0,%1,%2,%3}, {%4,%5,%6,%7}, {%8,%9}, {%0,%1,%2,%3};"
                 : "+f"(d[0]), "+f"(d[1]), "+f"(d[2]), "+f"(d[3])
                 : "r"(a[0]), "r"(a[1]), "r"(a[2]), "r"(a[3]), "r"(b0), "r"(b1));
}

// ---------------------------------------------------------------------------
// Layer-1 input conv (Cin=5, 5x5 VALID, 64x64 -> 60x60, Co=512), FFMA fp32.
// ---------------------------------------------------------------------------
__global__ __launch_bounds__(256, 2)
void conv_gemm_l1(const float* __restrict__ X, const float* __restrict__ W,
                  const float* __restrict__ bias, float* __restrict__ Out)
{
    __shared__ __align__(16) float As[16][128];
    __shared__ __align__(16) float Bs[16][128];
    __shared__ int sY[128], sX[128], sBase[128];

    const int t  = threadIdx.x;
    const int m0 = blockIdx.x * 128;
    const int n0 = blockIdx.y * 128;
    const int P  = 3600;

    if (t < 128) {
        int pix = m0 + t;
        int n = pix / P;
        int r = pix - n * P;
        int y = r / 60;
        sY[t] = y;
        sX[t] = r - y * 60;
        sBase[t] = n * 64 * 64 * 5;
    }
    __syncthreads();

    float acc[8][8];
    #pragma unroll
    for (int i = 0; i < 8; ++i)
        #pragma unroll
        for (int j = 0; j < 8; ++j) acc[i][j] = 0.f;

    const int tr = t & 15, tc = t >> 4;
    const int rowA = t >> 1;
    const int kk0  = (t & 1) * 8;
    const int aBase = sBase[rowA];
    const int aY = sY[rowA], aX = sX[rowA];

    for (int kt = 0; kt < 8; ++kt) {
        __syncthreads();
        #pragma unroll
        for (int j = 0; j < 8; ++j) {
            int kk = kk0 + j;
            int k  = kt * 16 + kk;
            float v = 0.f;
            if (k < 125) {
                int kp = k / 5;
                int c  = k - kp * 5;
                int ky = kp / 5;
                int kx = kp - ky * 5;
                v = X[aBase + ((aY + ky) * 64 + (aX + kx)) * 5 + c];
            }
            As[kk][rowA ^ ((kk >> 2) << 3)] = v;
        }
        #pragma unroll
        for (int it = 0; it < 2; ++it) {
            int idx = t + it * 256;
            int kk  = idx >> 5;
            int col = (idx & 31) << 2;
            int k   = kt * 16 + kk;
            float4 v = make_float4(0.f, 0.f, 0.f, 0.f);
            if (k < 125)
                v = *(const float4*)(W + (size_t)k * 512 + n0 + col);
            *(float4*)&Bs[kk][col] = v;
        }
        __syncthreads();
        #pragma unroll
        for (int kk = 0; kk < 16; ++kk) {
            const int sw = (kk & 12) << 1;
            float4 a0 = *(const float4*)&As[kk][(tr * 8) ^ sw];
            float4 a1 = *(const float4*)&As[kk][((tr * 8) ^ sw) + 4];
            float4 b0 = *(const float4*)&Bs[kk][tc * 8];
            float4 b1 = *(const float4*)&Bs[kk][tc * 8 + 4];
            float a[8] = {a0.x, a0.y, a0.z, a0.w, a1.x, a1.y, a1.z, a1.w};
            float b[8] = {b0.x, b0.y, b0.z, b0.w, b1.x, b1.y, b1.z, b1.w};
            #pragma unroll
            for (int i = 0; i < 8; ++i)
                #pragma unroll
                for (int j = 0; j < 8; ++j)
                    acc[i][j] = fmaf(a[i], b[j], acc[i][j]);
        }
    }

    float bv[8];
    #pragma unroll
    for (int j = 0; j < 8; ++j) bv[j] = bias[n0 + tc * 8 + j];
    #pragma unroll
    for (int i = 0; i < 8; ++i) {
        int pix = m0 + tr * 8 + i;
        int n = pix / P;
        int p = pix - n * P;
        int b = n / 6;
        int tt = n - b * 6;
        size_t ob = ((size_t)(tt * 16 + b) * P + p) * 512 + n0 + tc * 8;
        #pragma unroll
        for (int j4 = 0; j4 < 8; j4 += 4) {
            float4 o;
            o.x = acc[i][j4 + 0] + bv[j4 + 0];
            o.y = acc[i][j4 + 1] + bv[j4 + 1];
            o.z = acc[i][j4 + 2] + bv[j4 + 2];
            o.w = acc[i][j4 + 3] + bv[j4 + 3];
            *(float4*)(Out + ob + j4) = o;
        }
    }
}

// ---------------------------------------------------------------------------
// Weight prep: fp32 W [kp][c][Co] -> [chunk][Co rows][128B] swizzled images.
// Row n of chunk c: 16B slots [hi k0..31 | lo k0..31] in fp16, slot ^ (n&7).
// (lo slots retained in layout; unused by the 2-pass compute.)
// ---------------------------------------------------------------------------
__global__ void wprep_kernel(const float* __restrict__ W, __half* __restrict__ Wp,
                             int Cin, int Co, int nchunk)
{
    int c = blockIdx.x;
    int cpk = Cin >> 5;
    int kp = c / cpk, c0 = (c - kp * cpk) << 5;
    for (int n = threadIdx.x; n < Co; n += blockDim.x) {
        __half* dst = Wp + ((size_t)c * Co + n) * 64;
        int sw = n & 7;
        for (int k = 0; k < 32; ++k) {
            float w = W[(size_t)(kp * Cin + c0 + k) * Co + n];
            __half hi = __float2half_rn(w);
            __half lo = __float2half_rn(w - __half2float(hi));
            int ch = k >> 3, off = k & 7;
            dst[(( ch      ^ sw) << 3) + off] = hi;
            dst[(((ch + 4) ^ sw) << 3) + off] = lo;
        }
    }
}

// ---------------------------------------------------------------------------
// Tensor-core implicit-GEMM conv, fp16x2 fp32 emulation (A = hi/lo fp16,
// B = hi fp16; dropped term a*(b - bh) ~ 2^-11 relative).
// ONE 512-thread CTA per SM, tile 128(M) x 256(N); 16 warps in 4m x 4n,
// warp tile 32x64.  R14 pipeline: 3-stage cp.async ring, 2 chunks per
// barrier pair (wait_group 1).  Per 16-K half: Ahi*Bhi, Alo*Bhi (2 passes).
// A-source: xbase = nbi*xsb + xoff (reads h straight from sequence buffers).
// Requires M%128==0, Co%256==0, Cin%32==0, nchunk even.
// ---------------------------------------------------------------------------
#define CM_STAGE 49152
#define CM_SMEM  (3 * CM_STAGE)

__global__ __launch_bounds__(512, 1)
void conv_mma(const __half* __restrict__ Xhi, const __half* __restrict__ Xlo,
              const __half* __restrict__ Wp,
              const float* __restrict__ bias, const float* __restrict__ addend,
              float* __restrict__ Out,
              int Hi, int Wi, int Cin, int Co, int Ho, int Wo,
              int pad, int T, int Bo, int nchunk, int cpkShift,
              int xsb, int xoff)
{
    extern __shared__ __align__(16) char smem[];
    const uint32_t sbase = (uint32_t)__cvta_generic_to_shared(smem);
    const int t = threadIdx.x;
    const int m0 = blockIdx.x * 128, n0 = blockIdx.y * 256;
    const int P = Ho * Wo;
    const int cpkMask = (1 << cpkShift) - 1;

    // A-loader identity: row r = t>>2, half = (t>>1)&1, quarter q0 = (t&1)*2
    const int r    = t >> 2;
    const int half = (t >> 1) & 1;
    const int q0   = (t & 1) * 2;
    const int pix  = m0 + r;
    const int nbi  = pix / P;
    const int rr   = pix - nbi * P;
    const int py   = rr / Wo;
    const int px   = rr - py * Wo;
    const __half* Xsrc = half ? Xlo : Xhi;
    const size_t xbase = (size_t)nbi * xsb + xoff;
    const uint32_t arow = (uint32_t)r * 128;
    const int rsw = r & 7;

    const int lane = t & 31, wid = t >> 5;
    const int warp_m = wid & 3, warp_n = wid >> 2;
    const int khStag = (wid & 1) << 1;

    float acc[2][8][4];
    #pragma unroll
    for (int i = 0; i < 2; ++i)
        #pragma unroll
        for (int j = 0; j < 8; ++j)
            #pragma unroll
            for (int k = 0; k < 4; ++k) acc[i][j][k] = 0.f;

    const int rA  = warp_m * 32 + (lane & 15);
    const int swA = rA & 7;
    const int rB  = warp_n * 64 + (lane & 7) + ((lane >> 4) << 3);
    const int swB = rB & 7;
    const int aSel = lane >> 4;
    const int bSel = (lane >> 3) & 1;

    auto issue_chunk = [&](int c, int s) {
        const uint32_t stg = sbase + (uint32_t)s * CM_STAGE;
        int kp = c >> cpkShift;
        int c0 = (c & cpkMask) << 5;
        int ky = kp / 5, kx = kp - ky * 5;
        int iy = py + ky - pad, ix = px + kx - pad;
        bool ok = ((unsigned)iy < (unsigned)Hi) && ((unsigned)ix < (unsigned)Wi);
        const char* src = (const char*)(Xsrc + (ok ? (xbase + (size_t)(iy * Wi + ix) * Cin + c0)
                                                   : (size_t)0));
        int sz = ok ? 16 : 0;
        #pragma unroll
        for (int i = 0; i < 2; ++i) {
            int q = q0 + i;
            int ch = ((half << 2) + q) ^ rsw;
            cp16z(stg + arow + ch * 16, src + q * 16, sz);
        }
        const char* bsrc = (const char*)Wp + ((size_t)c * Co + n0) * 128;
        const uint32_t bb = stg + 16384;
        #pragma unroll
        for (int i = 0; i < 4; ++i)
            cp16cg(bb + (t * 4 + i) * 16, bsrc + (t * 4 + i) * 16);
    };

    auto compute = [&](int s) {
        uint32_t As = sbase + (uint32_t)s * CM_STAGE;
        uint32_t Bs = As + 16384;
        #pragma unroll
        for (int it = 0; it < 2; ++it) {
            const int kh = khStag ^ (it << 1);
            uint32_t aH[2][4], aL[2][4], bH[4][4];
            // ---- load A hi + B hi ----
            {
                uint32_t aaddr = As + rA * 128 + ((((kh) + aSel) ^ swA) << 4);
                ldsm4(aH[0][0], aH[0][1], aH[0][2], aH[0][3], aaddr);
                ldsm4(aH[1][0], aH[1][1], aH[1][2], aH[1][3], aaddr + 2048);
            }
            #pragma unroll
            for (int nt = 0; nt < 4; ++nt) {
                uint32_t baddr = Bs + (rB + nt * 16) * 128 + ((((kh) + bSel) ^ swB) << 4);
                ldsm4(bH[nt][0], bH[nt][1], bH[nt][2], bH[nt][3], baddr);
            }
            // ---- pass 1: Ahi * Bhi ----
            #pragma unroll
            for (int j = 0; j < 8; ++j) {
                uint32_t b0 = bH[j >> 1][(j & 1) * 2];
                uint32_t b1 = bH[j >> 1][(j & 1) * 2 + 1];
                mma_fp16(acc[0][j], aH[0], b0, b1);
                mma_fp16(acc[1][j], aH[1], b0, b1);
            }
            // ---- load A lo, pass 2: Alo * Bhi ----
            {
                uint32_t aaddr = As + rA * 128 + ((((kh + 4) + aSel) ^ swA) << 4);
                ldsm4(aL[0][0], aL[0][1], aL[0][2], aL[0][3], aaddr);
                ldsm4(aL[1][0], aL[1][1], aL[1][2], aL[1][3], aaddr + 2048);
            }
            #pragma unroll
            for (int j = 0; j < 8; ++j) {
                uint32_t b0 = bH[j >> 1][(j & 1) * 2];
                uint32_t b1 = bH[j >> 1][(j & 1) * 2 + 1];
                mma_fp16(acc[0][j], aL[0], b0, b1);
                mma_fp16(acc[1][j], aL[1], b0, b1);
            }
        }
    };

    // ---- prologue: fill all 3 stages ----
    issue_chunk(0, 0); cp_commit();
    issue_chunk(1, 1); cp_commit();
    issue_chunk(2, 2); cp_commit();

    // ---- mainloop (R14 shape): 2 chunks per barrier pair, stage = c mod 3 ----
    int s = 0;
    for (int c = 0; c < nchunk; c += 2) {
        cp_wait1();
        __syncthreads();
        int s1 = (s + 1 == 3) ? 0 : s + 1;
        compute(s);
        compute(s1);
        __syncthreads();
        if (c + 3 < nchunk) { issue_chunk(c + 3, s);  cp_commit(); }
        if (c + 4 < nchunk) { issue_chunk(c + 4, s1); cp_commit(); }
        s = (s1 + 1 == 3) ? 0 : s1 + 1;
    }

    // ---- epilogue ----
    const int colB = n0 + warp_n * 64 + (lane & 3) * 2;
    #pragma unroll
    for (int mt = 0; mt < 2; ++mt) {
        int r0g = m0 + warp_m * 32 + mt * 16 + (lane >> 2);
        #pragma unroll
        for (int hrow = 0; hrow < 2; ++hrow) {
            int pix2 = r0g + hrow * 8;
            size_t opix;
            if (T > 1) {
                int nb2 = pix2 / P, p = pix2 - nb2 * P;
                int b = nb2 / T, tt = nb2 - b * T;
                opix = (size_t)(tt * Bo + b) * P + p;
            } else {
                opix = (size_t)pix2;
            }
            size_t rowoff = opix * Co;
            #pragma unroll
            for (int j = 0; j < 8; ++j) {
                int col = colB + j * 8;
                float v0 = acc[mt][j][hrow * 2 + 0];
                float v1 = acc[mt][j][hrow * 2 + 1];
                if (addend) {
                    float2 ad = *(const float2*)(addend + rowoff + col);
                    v0 += ad.x; v1 += ad.y;
                } else {
                    v0 += bias[col]; v1 += bias[col + 1];
                }
                *(float2*)(Out + rowoff + col) = make_float2(v0, v1);
            }
        }
    }
}

// ---------------------------------------------------------------------------
// LSTM gate pointwise (keras gate order i,f,c,o).  zeroC==1 -> c_prev = 0.
// h / hhi,hlo / hshi,hslo each written only when their pointer is non-null.
// ---------------------------------------------------------------------------
__device__ __forceinline__ float hsig(float x)
{
    return fminf(1.f, fmaxf(0.f, fmaf(x, 0.2f, 0.5f)));
}

__global__ __launch_bounds__(256)
void gates_kernel(const float* __restrict__ z, float* __restrict__ c,
                  float* __restrict__ h,
                  __half* __restrict__ hhi, __half* __restrict__ hlo,
                  __half* __restrict__ hshi, __half* __restrict__ hslo,
                  int total4, int F, int P, int T, int ts, int zeroC)
{
    int idx = blockIdx.x * blockDim.x + threadIdx.x;
    if (idx >= total4) return;
    int e   = idx << 2;
    int pix = e / F;
    int f   = e - pix * F;
    size_t zb = (size_t)pix * (F << 2) + f;
    float4 zi = *(const float4*)(z + zb);
    float4 zf = *(const float4*)(z + zb + F);
    float4 zc = *(const float4*)(z + zb + 2 * F);
    float4 zo = *(const float4*)(z + zb + 3 * F);
    float4 cn, hn;
    if (zeroC) {
        cn.x = hsig(zi.x) * tanhf(zc.x);
        cn.y = hsig(zi.y) * tanhf(zc.y);
        cn.z = hsig(zi.z) * tanhf(zc.z);
        cn.w = hsig(zi.w) * tanhf(zc.w);
    } else {
        float4 cp = *(const float4*)(c + e);
        cn.x = hsig(zf.x) * cp.x + hsig(zi.x) * tanhf(zc.x);
        cn.y = hsig(zf.y) * cp.y + hsig(zi.y) * tanhf(zc.y);
        cn.z = hsig(zf.z) * cp.z + hsig(zi.z) * tanhf(zc.z);
        cn.w = hsig(zf.w) * cp.w + hsig(zi.w) * tanhf(zc.w);
    }
    hn.x = hsig(zo.x) * tanhf(cn.x);
    hn.y = hsig(zo.y) * tanhf(cn.y);
    hn.z = hsig(zo.z) * tanhf(cn.z);
    hn.w = hsig(zo.w) * tanhf(cn.w);
    *(float4*)(c + e) = cn;
    if (h) *(float4*)(h + e) = hn;

    float hv[4] = {hn.x, hn.y, hn.z, hn.w};
    __half hi[4], lo[4];
    #pragma unroll
    for (int k = 0; k < 4; ++k) {
        hi[k] = __float2half_rn(hv[k]);
        lo[k] = __float2half_rn(hv[k] - __half2float(hi[k]));
    }
    if (hhi) {
        #pragma unroll
        for (int k = 0; k < 4; ++k) { hhi[e + k] = hi[k]; hlo[e + k] = lo[k]; }
    }
    if (hshi) {
        int b = pix / P;
        int p = pix - b * P;
        size_t hsi = ((size_t)(b * T + ts) * P + p) * F + f;
        #pragma unroll
        for (int k = 0; k < 4; ++k) { hshi[hsi + k] = hi[k]; hslo[hsi + k] = lo[k]; }
    }
}

// ---------------------------------------------------------------------------
// Dense head (fp32, split-K, deterministic reduce)
// ---------------------------------------------------------------------------
__global__ __launch_bounds__(256)
void dense_splitk(const float* __restrict__ A, const float* __restrict__ Wt,
                  float* __restrict__ part, int K, int N, int kc)
{
    int col = blockIdx.x * 256 + threadIdx.x;
    int k0  = blockIdx.y * kc;
    int k1  = min(k0 + kc, K);
    float acc[16];
    #pragma unroll
    for (int b = 0; b < 16; ++b) acc[b] = 0.f;
    for (int k = k0; k < k1; ++k) {
        float w = Wt[(size_t)k * N + col];
        #pragma unroll
        for (int b = 0; b < 16; ++b)
            acc[b] = fmaf(A[(size_t)b * K + k], w, acc[b]);
    }
    size_t ob = (size_t)blockIdx.y * 16 * N;
    #pragma unroll
    for (int b = 0; b < 16; ++b)
        part[ob + (size_t)b * N + col] = acc[b];
}

__global__ __launch_bounds__(256)
void dense_reduce(const float* __restrict__ part, const float* __restrict__ bias,
                  float* __restrict__ out, int nsplit, int N, int do_relu)
{
    int i = blockIdx.x * blockDim.x + threadIdx.x;
    if (i >= 16 * N) return;
    float s = bias[i % N];
    for (int sp = 0; sp < nsplit; ++sp)
        s += part[(size_t)sp * 16 * N + i];
    out[i] = do_relu ? fmaxf(s, 0.f) : s;
}

__global__ void dense3_kernel(const float* __restrict__ A, const float* __restrict__ Wt,
                              const float* __restrict__ bias, float* __restrict__ out)
{
    int t = threadIdx.x;
    if (t >= 64) return;
    int b = t >> 2, n = t & 3;
    float acc = bias[n];
    #pragma unroll 8
    for (int k = 0; k < 1024; ++k)
        acc = fmaf(A[b * 1024 + k], Wt[k * 4 + n], acc);
    out[b * 4 + n] = acc;
}

// ---------------------------------------------------------------------------
// Host orchestration
// ---------------------------------------------------------------------------
static void recurrent_part(const float* Wh, __half* wp,
                           float* xz, float* zb, float* hb, float* cb,
                           __half* hhi, __half* hlo,
                           __half* hshi, __half* hslo,
                           int B, int T, int Ho, int Wo, int F, int needH)
{
    const int Cin = F, Co = 4 * F, P = Ho * Wo;
    const int nchunk = 25 * (Cin >> 5);
    const int shift  = (Cin == 128) ? 2 : 1;
    wprep_kernel<<<nchunk, 256>>>(Wh, wp, Cin, Co, nchunk);
    const int nstate = B * P * F;
    const int tot4 = nstate / 4;
    for (int t = 0; t < T; ++t) {
        const float* zp;
        if (t == 0) {
            zp = xz;
        } else {
            const __half *ahi, *alo;
            int xsb, xoff;
            if (hshi) {             // layers 1-2: read h from sequence buffer
                ahi = hshi; alo = hslo;
                xsb = T * P * F; xoff = (t - 1) * P * F;
            } else {                // layer 3: dedicated state buffer
                ahi = hhi; alo = hlo;
                xsb = P * F; xoff = 0;
            }
            conv_mma<<<dim3(B * P / 128, Co / 256), 512, CM_SMEM>>>(
                ahi, alo, wp, nullptr, xz + (size_t)t * B * P * Co, zb,
                Ho, Wo, Cin, Co, Ho, Wo, 2, 1, B, nchunk, shift, xsb, xoff);
            zp = zb;
        }
        float* hout = (needH && t == T - 1) ? hb : nullptr;
        __half* sthi = hshi ? nullptr : hhi;
        __half* stlo = hshi ? nullptr : hlo;
        gates_kernel<<<(tot4 + 255) / 256, 256>>>(zp, cb, hout, sthi, stlo,
                                                  hshi, hslo, tot4, F, P, T, t, t == 0);
    }
}

extern "C" void kernel_launch(void* const* d_in, const int* in_sizes, int n_in,
                              void* d_out, int out_size)
{
    (void)in_sizes; (void)n_in; (void)out_size;
    const float* x   = (const float*)d_in[0];
    const float* Wx1 = (const float*)d_in[1];
    const float* Wh1 = (const float*)d_in[2];
    const float* b1  = (const float*)d_in[3];
    const float* Wx2 = (const float*)d_in[4];
    const float* Wh2 = (const float*)d_in[5];
    const float* b2  = (const float*)d_in[6];
    const float* Wx3 = (const float*)d_in[7];
    const float* Wh3 = (const float*)d_in[8];
    const float* b3  = (const float*)d_in[9];
    const float* Wd1 = (const float*)d_in[10];
    const float* bd1 = (const float*)d_in[11];
    const float* Wd2 = (const float*)d_in[12];
    const float* bd2 = (const float*)d_in[13];
    const float* Wd3 = (const float*)d_in[14];
    const float* bd3 = (const float*)d_in[15];
    float* out = (float*)d_out;

    float *xz, *zb, *hb, *cb, *dp, *dd1, *dd2;
    __half *hhi, *hlo, *hs1hi, *hs1lo, *hs2hi, *hs2lo, *wp;
    cudaGetSymbolAddress((void**)&xz,    g_xz);
    cudaGetSymbolAddress((void**)&zb,    g_z);
    cudaGetSymbolAddress((void**)&hb,    g_h);
    cudaGetSymbolAddress((void**)&cb,    g_c);
    cudaGetSymbolAddress((void**)&hhi,   g_hhi);
    cudaGetSymbolAddress((void**)&hlo,   g_hlo);
    cudaGetSymbolAddress((void**)&hs1hi, g_hs1hi);
    cudaGetSymbolAddress((void**)&hs1lo, g_hs1lo);
    cudaGetSymbolAddress((void**)&hs2hi, g_hs2hi);
    cudaGetSymbolAddress((void**)&hs2lo, g_hs2lo);
    cudaGetSymbolAddress((void**)&wp,    g_wp);
    cudaGetSymbolAddress((void**)&dp,    g_dp);
    cudaGetSymbolAddress((void**)&dd1,   g_d1);
    cudaGetSymbolAddress((void**)&dd2,   g_d2);

    cudaFuncSetAttribute(conv_mma, cudaFuncAttributeMaxDynamicSharedMemorySize, CM_SMEM);

    const int B = 16, T = 6;

    // ---- layer 1: (B,T,64,64,5) -> seq (B,T,60,60,128) ----
    conv_gemm_l1<<<dim3(B * T * 3600 / 128, 4), 256>>>(x, Wx1, b1, xz);
    recurrent_part(Wh1, wp, xz, zb, hb, cb, hhi, hlo, hs1hi, hs1lo,
                   B, T, 60, 60, 128, 0);

    // ---- layer 2: seq1 -> seq (B,T,56,56,64) ----
    wprep_kernel<<<100, 256>>>(Wx2, wp, 128, 256, 100);
    conv_mma<<<dim3(B * T * 3136 / 128, 1), 512, CM_SMEM>>>(
        hs1hi, hs1lo, wp, b2, nullptr, xz, 60, 60, 128, 256, 56, 56, 0, T, B, 100, 2,
        60 * 60 * 128, 0);
    recurrent_part(Wh2, wp, xz, zb, hb, cb, hhi, hlo, hs2hi, hs2lo,
                   B, T, 56, 56, 64, 0);

    // ---- layer 3: seq2 -> final h (B,52,52,64) ----
    wprep_kernel<<<50, 256>>>(Wx3, wp, 64, 256, 50);
    conv_mma<<<dim3(B * T * 2704 / 128, 1), 512, CM_SMEM>>>(
        hs2hi, hs2lo, wp, b3, nullptr, xz, 56, 56, 64, 256, 52, 52, 0, T, B, 50, 1,
        56 * 56 * 64, 0);
    recurrent_part(Wh3, wp, xz, zb, hb, cb, hhi, hlo, nullptr, nullptr,
                   B, T, 52, 52, 64, 1);

    // ---- dense head ----
    dense_splitk<<<dim3(4, 64), 256>>>(hb, Wd1, dp, 173056, 1024, 2704);
    dense_reduce<<<64, 256>>>(dp, bd1, dd1, 64, 1024, 1);
    dense_splitk<<<dim3(4, 8), 256>>>(dd1, Wd2, dp, 1024, 1024, 128);
    dense_reduce<<<64, 256>>>(dp, bd2, dd2, 8, 1024, 1);
    dense3_kernel<<<1, 64>>>(dd2, Wd3, bd3, out);
}

// round 17
// speedup vs baseline: 2.2016x; 1.2185x over previous
#include <cuda_runtime.h>
#include <cuda_fp16.h>
#include <cstdint>

// ---------------------------------------------------------------------------
// Scratch (static __device__ arrays; no allocation anywhere)
// ---------------------------------------------------------------------------
__device__ float g_xz[176947200];            // time-major xz, max layer1: 96*3600*512
__device__ float g_z[29491200];              // recurrent pre-activation, max 16*3600*512
__device__ float g_h[7372800];               // fp32 h state (dense head input)
__device__ float g_c[7372800];               // c state
__device__ __half g_hhi[7372800];            // fp16 hi/lo h state (layer-3 conv input)
__device__ __half g_hlo[7372800];
__device__ __half g_hs1hi[44236800];         // layer1 output seq 96*3600*128
__device__ __half g_hs1lo[44236800];
__device__ __half g_hs2hi[19267584];         // layer2 output seq 96*3136*64
__device__ __half g_hs2lo[19267584];
__device__ __half g_wp[1638400];             // prepped weights [chunk][Co][32 fp16] hi-only
__device__ float g_dp[1048576];
__device__ float g_d1[16384];
__device__ float g_d2[16384];

// ---------------------------------------------------------------------------
// PTX helpers (portable subset only — no tcgen05 on this build's PTX target)
// ---------------------------------------------------------------------------
__device__ __forceinline__ void cp16cg(uint32_t dst, const void* src)
{
    asm volatile("cp.async.cg.shared.global [%0], [%1], 16;"
                 :: "r"(dst), "l"(src));
}
__device__ __forceinline__ void cp16z(uint32_t dst, const void* src, int sz)
{
    asm volatile("cp.async.cg.shared.global [%0], [%1], 16, %2;"
                 :: "r"(dst), "l"(src), "r"(sz));
}
__device__ __forceinline__ void cp_commit()
{
    asm volatile("cp.async.commit_group;" ::: "memory");
}
__device__ __forceinline__ void cp_wait1()
{
    asm volatile("cp.async.wait_group 1;" ::: "memory");
}

__device__ __forceinline__ void ldsm4(uint32_t& r0, uint32_t& r1, uint32_t& r2,
                                      uint32_t& r3, uint32_t addr)
{
    asm volatile("ldmatrix.sync.aligned.m8n8.x4.shared.b16 {%0,%1,%2,%3}, [%4];"
                 : "=r"(r0), "=r"(r1), "=r"(r2), "=r"(r3) : "r"(addr));
}

__device__ __forceinline__ void mma_fp16(float* d, const uint32_t* a,
                                         uint32_t b0, uint32_t b1)
{
    asm volatile("mma.sync.aligned.m16n8k16.row.col.f32.f16.f16.f32 "
                 "{%0,%1,%2,%3}, {%4,%5,%6,%7}, {%8,%9}, {%0,%1,%2,%3};"
                 : "+f"(d[0]), "+f"(d[1]), "+f"(d[2]), "+f"(d[3])
                 : "r"(a[0]), "r"(a[1]), "r"(a[2]), "r"(a[3]), "r"(b0), "r"(b1));
}

// ---------------------------------------------------------------------------
// Layer-1 input conv (Cin=5, 5x5 VALID, 64x64 -> 60x60, Co=512), FFMA fp32.
// ---------------------------------------------------------------------------
__global__ __launch_bounds__(256, 2)
void conv_gemm_l1(const float* __restrict__ X, const float* __restrict__ W,
                  const float* __restrict__ bias, float* __restrict__ Out)
{
    __shared__ __align__(16) float As[16][128];
    __shared__ __align__(16) float Bs[16][128];
    __shared__ int sY[128], sX[128], sBase[128];

    const int t  = threadIdx.x;
    const int m0 = blockIdx.x * 128;
    const int n0 = blockIdx.y * 128;
    const int P  = 3600;

    if (t < 128) {
        int pix = m0 + t;
        int n = pix / P;
        int r = pix - n * P;
        int y = r / 60;
        sY[t] = y;
        sX[t] = r - y * 60;
        sBase[t] = n * 64 * 64 * 5;
    }
    __syncthreads();

    float acc[8][8];
    #pragma unroll
    for (int i = 0; i < 8; ++i)
        #pragma unroll
        for (int j = 0; j < 8; ++j) acc[i][j] = 0.f;

    const int tr = t & 15, tc = t >> 4;
    const int rowA = t >> 1;
    const int kk0  = (t & 1) * 8;
    const int aBase = sBase[rowA];
    const int aY = sY[rowA], aX = sX[rowA];

    for (int kt = 0; kt < 8; ++kt) {
        __syncthreads();
        #pragma unroll
        for (int j = 0; j < 8; ++j) {
            int kk = kk0 + j;
            int k  = kt * 16 + kk;
            float v = 0.f;
            if (k < 125) {
                int kp = k / 5;
                int c  = k - kp * 5;
                int ky = kp / 5;
                int kx = kp - ky * 5;
                v = X[aBase + ((aY + ky) * 64 + (aX + kx)) * 5 + c];
            }
            As[kk][rowA ^ ((kk >> 2) << 3)] = v;
        }
        #pragma unroll
        for (int it = 0; it < 2; ++it) {
            int idx = t + it * 256;
            int kk  = idx >> 5;
            int col = (idx & 31) << 2;
            int k   = kt * 16 + kk;
            float4 v = make_float4(0.f, 0.f, 0.f, 0.f);
            if (k < 125)
                v = *(const float4*)(W + (size_t)k * 512 + n0 + col);
            *(float4*)&Bs[kk][col] = v;
        }
        __syncthreads();
        #pragma unroll
        for (int kk = 0; kk < 16; ++kk) {
            const int sw = (kk & 12) << 1;
            float4 a0 = *(const float4*)&As[kk][(tr * 8) ^ sw];
            float4 a1 = *(const float4*)&As[kk][((tr * 8) ^ sw) + 4];
            float4 b0 = *(const float4*)&Bs[kk][tc * 8];
            float4 b1 = *(const float4*)&Bs[kk][tc * 8 + 4];
            float a[8] = {a0.x, a0.y, a0.z, a0.w, a1.x, a1.y, a1.z, a1.w};
            float b[8] = {b0.x, b0.y, b0.z, b0.w, b1.x, b1.y, b1.z, b1.w};
            #pragma unroll
            for (int i = 0; i < 8; ++i)
                #pragma unroll
                for (int j = 0; j < 8; ++j)
                    acc[i][j] = fmaf(a[i], b[j], acc[i][j]);
        }
    }

    float bv[8];
    #pragma unroll
    for (int j = 0; j < 8; ++j) bv[j] = bias[n0 + tc * 8 + j];
    #pragma unroll
    for (int i = 0; i < 8; ++i) {
        int pix = m0 + tr * 8 + i;
        int n = pix / P;
        int p = pix - n * P;
        int b = n / 6;
        int tt = n - b * 6;
        size_t ob = ((size_t)(tt * 16 + b) * P + p) * 512 + n0 + tc * 8;
        #pragma unroll
        for (int j4 = 0; j4 < 8; j4 += 4) {
            float4 o;
            o.x = acc[i][j4 + 0] + bv[j4 + 0];
            o.y = acc[i][j4 + 1] + bv[j4 + 1];
            o.z = acc[i][j4 + 2] + bv[j4 + 2];
            o.w = acc[i][j4 + 3] + bv[j4 + 3];
            *(float4*)(Out + ob + j4) = o;
        }
    }
}

// ---------------------------------------------------------------------------
// Weight prep: fp32 W [kp][c][Co] -> [chunk][Co rows][64B] hi-only images.
// Row n of chunk c: 4 x 16B slots [k0-7|k8-15|k16-23|k24-31], fp16 hi,
// slot index ^ ((n>>1)&3)  (conflict-free for 8-row ldsm groups).
// ---------------------------------------------------------------------------
__global__ void wprep_kernel(const float* __restrict__ W, __half* __restrict__ Wp,
                             int Cin, int Co, int nchunk)
{
    int c = blockIdx.x;
    int cpk = Cin >> 5;
    int kp = c / cpk, c0 = (c - kp * cpk) << 5;
    for (int n = threadIdx.x; n < Co; n += blockDim.x) {
        __half* dst = Wp + ((size_t)c * Co + n) * 32;
        int sw = (n >> 1) & 3;
        for (int k = 0; k < 32; ++k) {
            float w = W[(size_t)(kp * Cin + c0 + k) * Co + n];
            int ch = k >> 3, off = k & 7;
            dst[((ch ^ sw) << 3) + off] = __float2half_rn(w);
        }
    }
}

// ---------------------------------------------------------------------------
// Tensor-core implicit-GEMM conv, fp16x2 fp32 emulation (A = hi/lo fp16,
// B = hi fp16 only; dropped term a*(b - bh) ~ 2^-11 relative).
// ONE 512-thread CTA per SM, tile 128(M) x 256(N); 16 warps in 4m x 4n,
// warp tile 32x64.  3-stage cp.async ring (stage = A 16KB + B 16KB = 32KB),
// 2 chunks per barrier pair (wait_group 1).  B images are hi-only 64B rows.
// A-source: xbase = nbi*xsb + xoff (reads h straight from sequence buffers).
// Requires M%128==0, Co%256==0, Cin%32==0, nchunk even.
// ---------------------------------------------------------------------------
#define CM_STAGE 32768
#define CM_SMEM  (3 * CM_STAGE)

__global__ __launch_bounds__(512, 1)
void conv_mma(const __half* __restrict__ Xhi, const __half* __restrict__ Xlo,
              const __half* __restrict__ Wp,
              const float* __restrict__ bias, const float* __restrict__ addend,
              float* __restrict__ Out,
              int Hi, int Wi, int Cin, int Co, int Ho, int Wo,
              int pad, int T, int Bo, int nchunk, int cpkShift,
              int xsb, int xoff)
{
    extern __shared__ __align__(16) char smem[];
    const uint32_t sbase = (uint32_t)__cvta_generic_to_shared(smem);
    const int t = threadIdx.x;
    const int m0 = blockIdx.x * 128, n0 = blockIdx.y * 256;
    const int P = Ho * Wo;
    const int cpkMask = (1 << cpkShift) - 1;

    // A-loader identity: row r = t>>2, half = (t>>1)&1, quarter q0 = (t&1)*2
    const int r    = t >> 2;
    const int half = (t >> 1) & 1;
    const int q0   = (t & 1) * 2;
    const int pix  = m0 + r;
    const int nbi  = pix / P;
    const int rr   = pix - nbi * P;
    const int py   = rr / Wo;
    const int px   = rr - py * Wo;
    const __half* Xsrc = half ? Xlo : Xhi;
    const size_t xbase = (size_t)nbi * xsb + xoff;
    const uint32_t arow = (uint32_t)r * 128;
    const int rsw = r & 7;

    const int lane = t & 31, wid = t >> 5;
    const int warp_m = wid & 3, warp_n = wid >> 2;
    const int khStag = (wid & 1) << 1;

    float acc[2][8][4];
    #pragma unroll
    for (int i = 0; i < 2; ++i)
        #pragma unroll
        for (int j = 0; j < 8; ++j)
            #pragma unroll
            for (int k = 0; k < 4; ++k) acc[i][j][k] = 0.f;

    const int rA  = warp_m * 32 + (lane & 15);
    const int swA = rA & 7;
    const int rB  = warp_n * 64 + (lane & 7) + ((lane >> 4) << 3);
    const int swB = (rB >> 1) & 3;          // 64B-row swizzle (constant over nt)
    const int aSel = lane >> 4;
    const int bSel = (lane >> 3) & 1;

    auto issue_chunk = [&](int c, int s) {
        const uint32_t stg = sbase + (uint32_t)s * CM_STAGE;
        int kp = c >> cpkShift;
        int c0 = (c & cpkMask) << 5;
        int ky = kp / 5, kx = kp - ky * 5;
        int iy = py + ky - pad, ix = px + kx - pad;
        bool ok = ((unsigned)iy < (unsigned)Hi) && ((unsigned)ix < (unsigned)Wi);
        const char* src = (const char*)(Xsrc + (ok ? (xbase + (size_t)(iy * Wi + ix) * Cin + c0)
                                                   : (size_t)0));
        int sz = ok ? 16 : 0;
        #pragma unroll
        for (int i = 0; i < 2; ++i) {
            int q = q0 + i;
            int ch = ((half << 2) + q) ^ rsw;
            cp16z(stg + arow + ch * 16, src + q * 16, sz);
        }
        // B: 256 rows x 64B = 16KB; 512 threads x 2 x 16B
        const char* bsrc = (const char*)Wp + ((size_t)c * Co + n0) * 64;
        const uint32_t bb = stg + 16384;
        cp16cg(bb + t * 32,      bsrc + t * 32);
        cp16cg(bb + t * 32 + 16, bsrc + t * 32 + 16);
    };

    auto compute = [&](int s) {
        uint32_t As = sbase + (uint32_t)s * CM_STAGE;
        uint32_t Bs = As + 16384;
        #pragma unroll
        for (int it = 0; it < 2; ++it) {
            const int kh = khStag ^ (it << 1);
            uint32_t aH[2][4], aL[2][4], bH[4][4];
            // ---- load A hi + B hi ----
            {
                uint32_t aaddr = As + rA * 128 + ((((kh) + aSel) ^ swA) << 4);
                ldsm4(aH[0][0], aH[0][1], aH[0][2], aH[0][3], aaddr);
                ldsm4(aH[1][0], aH[1][1], aH[1][2], aH[1][3], aaddr + 2048);
            }
            #pragma unroll
            for (int nt = 0; nt < 4; ++nt) {
                uint32_t baddr = Bs + (rB + nt * 16) * 64 + ((((kh) + bSel) ^ swB) << 4);
                ldsm4(bH[nt][0], bH[nt][1], bH[nt][2], bH[nt][3], baddr);
            }
            // ---- pass 1: Ahi * Bhi ----
            #pragma unroll
            for (int j = 0; j < 8; ++j) {
                uint32_t b0 = bH[j >> 1][(j & 1) * 2];
                uint32_t b1 = bH[j >> 1][(j & 1) * 2 + 1];
                mma_fp16(acc[0][j], aH[0], b0, b1);
                mma_fp16(acc[1][j], aH[1], b0, b1);
            }
            // ---- load A lo, pass 2: Alo * Bhi ----
            {
                uint32_t aaddr = As + rA * 128 + ((((kh + 4) + aSel) ^ swA) << 4);
                ldsm4(aL[0][0], aL[0][1], aL[0][2], aL[0][3], aaddr);
                ldsm4(aL[1][0], aL[1][1], aL[1][2], aL[1][3], aaddr + 2048);
            }
            #pragma unroll
            for (int j = 0; j < 8; ++j) {
                uint32_t b0 = bH[j >> 1][(j & 1) * 2];
                uint32_t b1 = bH[j >> 1][(j & 1) * 2 + 1];
                mma_fp16(acc[0][j], aL[0], b0, b1);
                mma_fp16(acc[1][j], aL[1], b0, b1);
            }
        }
    };

    // ---- prologue: fill all 3 stages ----
    issue_chunk(0, 0); cp_commit();
    issue_chunk(1, 1); cp_commit();
    issue_chunk(2, 2); cp_commit();

    // ---- mainloop: 2 chunks per barrier pair, stage = c mod 3 ----
    int s = 0;
    for (int c = 0; c < nchunk; c += 2) {
        cp_wait1();
        __syncthreads();
        int s1 = (s + 1 == 3) ? 0 : s + 1;
        compute(s);
        compute(s1);
        __syncthreads();
        if (c + 3 < nchunk) { issue_chunk(c + 3, s);  cp_commit(); }
        if (c + 4 < nchunk) { issue_chunk(c + 4, s1); cp_commit(); }
        s = (s1 + 1 == 3) ? 0 : s1 + 1;
    }

    // ---- epilogue ----
    const int colB = n0 + warp_n * 64 + (lane & 3) * 2;
    #pragma unroll
    for (int mt = 0; mt < 2; ++mt) {
        int r0g = m0 + warp_m * 32 + mt * 16 + (lane >> 2);
        #pragma unroll
        for (int hrow = 0; hrow < 2; ++hrow) {
            int pix2 = r0g + hrow * 8;
            size_t opix;
            if (T > 1) {
                int nb2 = pix2 / P, p = pix2 - nb2 * P;
                int b = nb2 / T, tt = nb2 - b * T;
                opix = (size_t)(tt * Bo + b) * P + p;
            } else {
                opix = (size_t)pix2;
            }
            size_t rowoff = opix * Co;
            #pragma unroll
            for (int j = 0; j < 8; ++j) {
                int col = colB + j * 8;
                float v0 = acc[mt][j][hrow * 2 + 0];
                float v1 = acc[mt][j][hrow * 2 + 1];
                if (addend) {
                    float2 ad = *(const float2*)(addend + rowoff + col);
                    v0 += ad.x; v1 += ad.y;
                } else {
                    v0 += bias[col]; v1 += bias[col + 1];
                }
                *(float2*)(Out + rowoff + col) = make_float2(v0, v1);
            }
        }
    }
}

// ---------------------------------------------------------------------------
// LSTM gate pointwise (keras gate order i,f,c,o).  zeroC==1 -> c_prev = 0.
// h / hhi,hlo / hshi,hslo each written only when their pointer is non-null.
// ---------------------------------------------------------------------------
__device__ __forceinline__ float hsig(float x)
{
    return fminf(1.f, fmaxf(0.f, fmaf(x, 0.2f, 0.5f)));
}

__global__ __launch_bounds__(256)
void gates_kernel(const float* __restrict__ z, float* __restrict__ c,
                  float* __restrict__ h,
                  __half* __restrict__ hhi, __half* __restrict__ hlo,
                  __half* __restrict__ hshi, __half* __restrict__ hslo,
                  int total4, int F, int P, int T, int ts, int zeroC)
{
    int idx = blockIdx.x * blockDim.x + threadIdx.x;
    if (idx >= total4) return;
    int e   = idx << 2;
    int pix = e / F;
    int f   = e - pix * F;
    size_t zb = (size_t)pix * (F << 2) + f;
    float4 zi = *(const float4*)(z + zb);
    float4 zf = *(const float4*)(z + zb + F);
    float4 zc = *(const float4*)(z + zb + 2 * F);
    float4 zo = *(const float4*)(z + zb + 3 * F);
    float4 cn, hn;
    if (zeroC) {
        cn.x = hsig(zi.x) * tanhf(zc.x);
        cn.y = hsig(zi.y) * tanhf(zc.y);
        cn.z = hsig(zi.z) * tanhf(zc.z);
        cn.w = hsig(zi.w) * tanhf(zc.w);
    } else {
        float4 cp = *(const float4*)(c + e);
        cn.x = hsig(zf.x) * cp.x + hsig(zi.x) * tanhf(zc.x);
        cn.y = hsig(zf.y) * cp.y + hsig(zi.y) * tanhf(zc.y);
        cn.z = hsig(zf.z) * cp.z + hsig(zi.z) * tanhf(zc.z);
        cn.w = hsig(zf.w) * cp.w + hsig(zi.w) * tanhf(zc.w);
    }
    hn.x = hsig(zo.x) * tanhf(cn.x);
    hn.y = hsig(zo.y) * tanhf(cn.y);
    hn.z = hsig(zo.z) * tanhf(cn.z);
    hn.w = hsig(zo.w) * tanhf(cn.w);
    *(float4*)(c + e) = cn;
    if (h) *(float4*)(h + e) = hn;

    float hv[4] = {hn.x, hn.y, hn.z, hn.w};
    __half hi[4], lo[4];
    #pragma unroll
    for (int k = 0; k < 4; ++k) {
        hi[k] = __float2half_rn(hv[k]);
        lo[k] = __float2half_rn(hv[k] - __half2float(hi[k]));
    }
    if (hhi) {
        #pragma unroll
        for (int k = 0; k < 4; ++k) { hhi[e + k] = hi[k]; hlo[e + k] = lo[k]; }
    }
    if (hshi) {
        int b = pix / P;
        int p = pix - b * P;
        size_t hsi = ((size_t)(b * T + ts) * P + p) * F + f;
        #pragma unroll
        for (int k = 0; k < 4; ++k) { hshi[hsi + k] = hi[k]; hslo[hsi + k] = lo[k]; }
    }
}

// ---------------------------------------------------------------------------
// Dense head (fp32, split-K, deterministic reduce)
// ---------------------------------------------------------------------------
__global__ __launch_bounds__(256)
void dense_splitk(const float* __restrict__ A, const float* __restrict__ Wt,
                  float* __restrict__ part, int K, int N, int kc)
{
    int col = blockIdx.x * 256 + threadIdx.x;
    int k0  = blockIdx.y * kc;
    int k1  = min(k0 + kc, K);
    float acc[16];
    #pragma unroll
    for (int b = 0; b < 16; ++b) acc[b] = 0.f;
    for (int k = k0; k < k1; ++k) {
        float w = Wt[(size_t)k * N + col];
        #pragma unroll
        for (int b = 0; b < 16; ++b)
            acc[b] = fmaf(A[(size_t)b * K + k], w, acc[b]);
    }
    size_t ob = (size_t)blockIdx.y * 16 * N;
    #pragma unroll
    for (int b = 0; b < 16; ++b)
        part[ob + (size_t)b * N + col] = acc[b];
}

__global__ __launch_bounds__(256)
void dense_reduce(const float* __restrict__ part, const float* __restrict__ bias,
                  float* __restrict__ out, int nsplit, int N, int do_relu)
{
    int i = blockIdx.x * blockDim.x + threadIdx.x;
    if (i >= 16 * N) return;
    float s = bias[i % N];
    for (int sp = 0; sp < nsplit; ++sp)
        s += part[(size_t)sp * 16 * N + i];
    out[i] = do_relu ? fmaxf(s, 0.f) : s;
}

__global__ void dense3_kernel(const float* __restrict__ A, const float* __restrict__ Wt,
                              const float* __restrict__ bias, float* __restrict__ out)
{
    int t = threadIdx.x;
    if (t >= 64) return;
    int b = t >> 2, n = t & 3;
    float acc = bias[n];
    #pragma unroll 8
    for (int k = 0; k < 1024; ++k)
        acc = fmaf(A[b * 1024 + k], Wt[k * 4 + n], acc);
    out[b * 4 + n] = acc;
}

// ---------------------------------------------------------------------------
// Host orchestration
// ---------------------------------------------------------------------------
static void recurrent_part(const float* Wh, __half* wp,
                           float* xz, float* zb, float* hb, float* cb,
                           __half* hhi, __half* hlo,
                           __half* hshi, __half* hslo,
                           int B, int T, int Ho, int Wo, int F, int needH)
{
    const int Cin = F, Co = 4 * F, P = Ho * Wo;
    const int nchunk = 25 * (Cin >> 5);
    const int shift  = (Cin == 128) ? 2 : 1;
    wprep_kernel<<<nchunk, 256>>>(Wh, wp, Cin, Co, nchunk);
    const int nstate = B * P * F;
    const int tot4 = nstate / 4;
    for (int t = 0; t < T; ++t) {
        const float* zp;
        if (t == 0) {
            zp = xz;
        } else {
            const __half *ahi, *alo;
            int xsb, xoff;
            if (hshi) {             // layers 1-2: read h from sequence buffer
                ahi = hshi; alo = hslo;
                xsb = T * P * F; xoff = (t - 1) * P * F;
            } else {                // layer 3: dedicated state buffer
                ahi = hhi; alo = hlo;
                xsb = P * F; xoff = 0;
            }
            conv_mma<<<dim3(B * P / 128, Co / 256), 512, CM_SMEM>>>(
                ahi, alo, wp, nullptr, xz + (size_t)t * B * P * Co, zb,
                Ho, Wo, Cin, Co, Ho, Wo, 2, 1, B, nchunk, shift, xsb, xoff);
            zp = zb;
        }
        float* hout = (needH && t == T - 1) ? hb : nullptr;
        __half* sthi = hshi ? nullptr : hhi;
        __half* stlo = hshi ? nullptr : hlo;
        gates_kernel<<<(tot4 + 255) / 256, 256>>>(zp, cb, hout, sthi, stlo,
                                                  hshi, hslo, tot4, F, P, T, t, t == 0);
    }
}

extern "C" void kernel_launch(void* const* d_in, const int* in_sizes, int n_in,
                              void* d_out, int out_size)
{
    (void)in_sizes; (void)n_in; (void)out_size;
    const float* x   = (const float*)d_in[0];
    const float* Wx1 = (const float*)d_in[1];
    const float* Wh1 = (const float*)d_in[2];
    const float* b1  = (const float*)d_in[3];
    const float* Wx2 = (const float*)d_in[4];
    const float* Wh2 = (const float*)d_in[5];
    const float* b2  = (const float*)d_in[6];
    const float* Wx3 = (const float*)d_in[7];
    const float* Wh3 = (const float*)d_in[8];
    const float* b3  = (const float*)d_in[9];
    const float* Wd1 = (const float*)d_in[10];
    const float* bd1 = (const float*)d_in[11];
    const float* Wd2 = (const float*)d_in[12];
    const float* bd2 = (const float*)d_in[13];
    const float* Wd3 = (const float*)d_in[14];
    const float* bd3 = (const float*)d_in[15];
    float* out = (float*)d_out;

    float *xz, *zb, *hb, *cb, *dp, *dd1, *dd2;
    __half *hhi, *hlo, *hs1hi, *hs1lo, *hs2hi, *hs2lo, *wp;
    cudaGetSymbolAddress((void**)&xz,    g_xz);
    cudaGetSymbolAddress((void**)&zb,    g_z);
    cudaGetSymbolAddress((void**)&hb,    g_h);
    cudaGetSymbolAddress((void**)&cb,    g_c);
    cudaGetSymbolAddress((void**)&hhi,   g_hhi);
    cudaGetSymbolAddress((void**)&hlo,   g_hlo);
    cudaGetSymbolAddress((void**)&hs1hi, g_hs1hi);
    cudaGetSymbolAddress((void**)&hs1lo, g_hs1lo);
    cudaGetSymbolAddress((void**)&hs2hi, g_hs2hi);
    cudaGetSymbolAddress((void**)&hs2lo, g_hs2lo);
    cudaGetSymbolAddress((void**)&wp,    g_wp);
    cudaGetSymbolAddress((void**)&dp,    g_dp);
    cudaGetSymbolAddress((void**)&dd1,   g_d1);
    cudaGetSymbolAddress((void**)&dd2,   g_d2);

    cudaFuncSetAttribute(conv_mma, cudaFuncAttributeMaxDynamicSharedMemorySize, CM_SMEM);

    const int B = 16, T = 6;

    // ---- layer 1: (B,T,64,64,5) -> seq (B,T,60,60,128) ----
    conv_gemm_l1<<<dim3(B * T * 3600 / 128, 4), 256>>>(x, Wx1, b1, xz);
    recurrent_part(Wh1, wp, xz, zb, hb, cb, hhi, hlo, hs1hi, hs1lo,
                   B, T, 60, 60, 128, 0);

    // ---- layer 2: seq1 -> seq (B,T,56,56,64) ----
    wprep_kernel<<<100, 256>>>(Wx2, wp, 128, 256, 100);
    conv_mma<<<dim3(B * T * 3136 / 128, 1), 512, CM_SMEM>>>(
        hs1hi, hs1lo, wp, b2, nullptr, xz, 60, 60, 128, 256, 56, 56, 0, T, B, 100, 2,
        60 * 60 * 128, 0);
    recurrent_part(Wh2, wp, xz, zb, hb, cb, hhi, hlo, hs2hi, hs2lo,
                   B, T, 56, 56, 64, 0);

    // ---- layer 3: seq2 -> final h (B,52,52,64) ----
    wprep_kernel<<<50, 256>>>(Wx3, wp, 64, 256, 50);
    conv_mma<<<dim3(B * T * 2704 / 128, 1), 512, CM_SMEM>>>(
        hs2hi, hs2lo, wp, b3, nullptr, xz, 56, 56, 64, 256, 52, 52, 0, T, B, 50, 1,
        56 * 56 * 64, 0);
    recurrent_part(Wh3, wp, xz, zb, hb, cb, hhi, hlo, nullptr, nullptr,
                   B, T, 52, 52, 64, 1);

    // ---- dense head ----
    dense_splitk<<<dim3(4, 64), 256>>>(hb, Wd1, dp, 173056, 1024, 2704);
    dense_reduce<<<64, 256>>>(dp, bd1, dd1, 64, 1024, 1);
    dense_splitk<<<dim3(4, 8), 256>>>(dd1, Wd2, dp, 1024, 1024, 128);
    dense_reduce<<<64, 256>>>(dp, bd2, dd2, 8, 1024, 1);
    dense3_kernel<<<1, 64>>>(dd2, Wd3, bd3, out);
}